// round 16
// baseline (speedup 1.0000x reference)
#include <cuda_runtime.h>
#include <cstdint>

#define NB    24
#define NP1   25
#define NCOST (NB * NP1)      // 600 floats per batch
#define ND    256
#define SPAD  260             // padded row stride (floats): 260 mod 32 = 4
#define INFX  1e9f
#define FULL  0xffffffffu
#define MAXB  2048

#define TILE_F4   (NB * ND / 4)          // 1536 float4 per tile
#define SMEM_COST (2 * NB * SPAD * 4 + 48 * 4)   // 50112 B

// cost scratch: [B][24][25] fp32 (~4.9 MB), static device array (no allocs)
__device__ float g_cost[(size_t)MAXB * NCOST];

// packed fp32x2 FMA (sm_100+); doubles are 64-bit carriers for f32 pairs
__device__ __forceinline__ double ffma2(double a, double b, double c) {
    double r;
    asm("fma.rn.f32x2 %0, %1, %2, %3;" : "=d"(r) : "d"(a), "d"(b), "d"(c));
    return r;
}
__device__ __forceinline__ float pairsum(double a) {
    return __int_as_float(__double2loint(a)) + __int_as_float(__double2hiint(a));
}
// order-preserving float<->uint for unsigned min-reduction
__device__ __forceinline__ unsigned fenc(float x) {
    unsigned b = __float_as_uint(x);
    return b ^ (((unsigned)((int)b >> 31)) | 0x80000000u);
}
__device__ __forceinline__ float fdec(unsigned k) {
    unsigned m = ((unsigned)((int)(~k) >> 31)) | 0x80000000u;
    return __uint_as_float(k ^ m);
}

// ============================================================================
// Kernel 1 (cost): CTA = one batch, 144 threads. Thread (i, jg) computes
// cost[i][j] for j = jg + 6m (m=0..3) via a serial k-loop over smem tiles.
// No warp reductions at all. Row stride SPAD=260 makes all main-loop LDS
// conflict-free: prev banks 4*i (distinct over the <=6 i's in a warp, rest
// broadcast), cur banks 4*jg + 24*m (disjoint 4-bank groups over jg).
// ============================================================================
__global__ __launch_bounds__(144) void costk(
    const float* __restrict__ slots,
    const float* __restrict__ prev,
    int B)
{
    extern __shared__ float smem[];
    float* cur_s  = smem;                        // 24 x 260
    float* prev_s = smem + NB * SPAD;            // 24 x 260
    float* icn_s  = smem + 2 * NB * SPAD;        // 24
    float* ipn_s  = icn_s + NB;                  // 24

    const int tid = threadIdx.x;
    const int b   = blockIdx.x;

    const float4* gs = (const float4*)(slots + (size_t)b * NB * ND);
    const float4* gp = (const float4*)(prev  + (size_t)b * NB * ND);

    // ---- stage both tiles into padded smem (coalesced reads) ----
    float4* cs4 = (float4*)cur_s;    // 65 float4 per row
    float4* ps4 = (float4*)prev_s;
    for (int idx = tid; idx < TILE_F4; idx += 144) {
        int row = idx >> 6;          // 64 float4 per source row
        int col = idx & 63;
        cs4[row * 65 + col] = gs[idx];
        ps4[row * 65 + col] = gp[idx];
    }
    __syncthreads();

    // ---- inverse norms: threads 0..47, one row each (serial, 4-acc ILP) ----
    if (tid < 48) {
        const float* rowp = (tid < NB) ? (cur_s + tid * SPAD)
                                       : (prev_s + (tid - NB) * SPAD);
        const double2* r2 = (const double2*)rowp;
        double a0 = 0.0, a1 = 0.0, a2 = 0.0, a3 = 0.0;
        #pragma unroll
        for (int t = 0; t < 64; t += 2) {
            double2 v0 = r2[t];
            double2 v1 = r2[t + 1];
            a0 = ffma2(v0.x, v0.x, a0);
            a1 = ffma2(v0.y, v0.y, a1);
            a2 = ffma2(v1.x, v1.x, a2);
            a3 = ffma2(v1.y, v1.y, a3);
        }
        float s = (pairsum(a0) + pairsum(a1)) + (pairsum(a2) + pairsum(a3));
        float inv = 1.0f / fmaxf(sqrtf(s), 1e-12f);
        if (tid < NB) icn_s[tid] = inv;
        else          ipn_s[tid - NB] = inv;
    }
    __syncthreads();

    // ---- main: 4 dots per thread, serial k, zero reductions ----
    const int i  = tid / 6;          // 0..23
    const int jg = tid % 6;          // 0..5
    const double2* pr = (const double2*)(prev_s + i * SPAD);
    const double2* c0 = (const double2*)(cur_s + jg * SPAD);
    const double2* c1 = (const double2*)(cur_s + (jg + 6) * SPAD);
    const double2* c2 = (const double2*)(cur_s + (jg + 12) * SPAD);
    const double2* c3 = (const double2*)(cur_s + (jg + 18) * SPAD);

    double A0x = 0.0, A0y = 0.0, A1x = 0.0, A1y = 0.0;
    double A2x = 0.0, A2y = 0.0, A3x = 0.0, A3y = 0.0;
    #pragma unroll 8
    for (int t = 0; t < 64; t++) {
        double2 p  = pr[t];
        double2 x0 = c0[t];
        double2 x1 = c1[t];
        double2 x2 = c2[t];
        double2 x3 = c3[t];
        A0x = ffma2(p.x, x0.x, A0x);  A0y = ffma2(p.y, x0.y, A0y);
        A1x = ffma2(p.x, x1.x, A1x);  A1y = ffma2(p.y, x1.y, A1y);
        A2x = ffma2(p.x, x2.x, A2x);  A2y = ffma2(p.y, x2.y, A2y);
        A3x = ffma2(p.x, x3.x, A3x);  A3y = ffma2(p.y, x3.y, A3y);
    }
    float d0 = pairsum(A0x) + pairsum(A0y);
    float d1 = pairsum(A1x) + pairsum(A1y);
    float d2 = pairsum(A2x) + pairsum(A2y);
    float d3 = pairsum(A3x) + pairsum(A3y);

    float ipn = ipn_s[i];
    float* gc = g_cost + (size_t)b * NCOST + i * NP1;
    gc[jg]      = 1.0f - d0 * ipn * icn_s[jg];
    gc[jg + 6]  = 1.0f - d1 * ipn * icn_s[jg + 6];
    gc[jg + 12] = 1.0f - d2 * ipn * icn_s[jg + 12];
    gc[jg + 18] = 1.0f - d3 * ipn * icn_s[jg + 18];
}

namespace {
struct AttrInit {
    AttrInit() {
        cudaFuncSetAttribute(costk, cudaFuncAttributeMaxDynamicSharedMemorySize,
                             SMEM_COST);
    }
};
AttrInit g_attr;
}

// ============================================================================
// Kernel 2: JV Hungarian + gather. One warp per batch, 4 warps/CTA.
// Byte-identical to the validated R10 version.
// ============================================================================
__global__ __launch_bounds__(128) void jvk(
    const float* __restrict__ slots,
    float* __restrict__ out,
    int B)
{
    __shared__ float cost_s[4][NCOST];
    __shared__ int   col_s[4][NB];

    const int lane = threadIdx.x & 31;
    const int w    = threadIdx.x >> 5;
    const int b    = blockIdx.x * 4 + w;
    if (b >= B) return;

    // ---- stage this batch's cost matrix into smem (600 floats) ----
    {
        const float4* gc4 = (const float4*)(g_cost + (size_t)b * NCOST);
        float4* cs4 = (float4*)cost_s[w];
        #pragma unroll
        for (int t = lane; t < NCOST / 4; t += 32)
            cs4[t] = gc4[t];
    }
    __syncwarp();

    const float* cw = cost_s[w];
    const unsigned ENC_INF = fenc(INFX);

    float u = 0.0f, v = 0.0f;
    int   p = -1;
    unsigned rowmask = 0;       // bit r set => row r matched

    // ---- column reduction: v[j] = min_i c[i][j]; greedy argmin matching ----
    {
        int rmin = 32 + lane;   // unique sentinel for lanes >= NB
        if (lane < NB) {
            float m = INFX;
            rmin = 0;
            #pragma unroll
            for (int i = 0; i < NB; i++) {
                float c = cw[i * NP1 + lane];
                if (c < m) { m = c; rmin = i; }   // first-index on ties
            }
            v = m;
        }
        unsigned grp = __match_any_sync(FULL, rmin);
        bool claim = (lane < NB) && (lane == __ffs(grp) - 1);  // lowest col wins row
        if (claim) p = rmin;
        rowmask = __reduce_or_sync(FULL, claim ? (1u << rmin) : 0u);
    }

    // ---- augmenting row reduction over still-free rows ----
    {
        unsigned freerows = ~rowmask & ((1u << NB) - 1u);
        while (freerows) {
            int i = __ffs(freerows) - 1;
            freerows &= freerows - 1;
            float rc = (lane < NB) ? cw[i * NP1 + lane] - v : INFX;
            unsigned key  = (lane < NB) ? fenc(rc) : ENC_INF;
            unsigned kmin = __reduce_min_sync(FULL, key);
            int j1 = __ffs(__ballot_sync(FULL, key == kmin)) - 1;
            float ui = fdec(kmin);
            if (lane == i) u = ui;
            int pj1 = __shfl_sync(FULL, p, j1);
            if (pj1 < 0) {                 // column free -> match (i, j1)
                if (lane == j1) p = i;
                rowmask |= 1u << i;
            }
        }
    }

    // ---- augmenting-path searches for remaining free rows (validated) ----
    for (int i = 0; i < NB; i++) {
        if ((rowmask >> i) & 1u) continue;

        if (lane == NB) p = i;
        float minv = INFX;
        int   way  = 0;
        bool  used = false;
        bool  row_used = false;
        int   j0  = NB;
        int   pj0 = i;

        while (true) {
            used     = used     || (lane == j0);
            row_used = row_used || (lane == pj0);
            float u_i0 = __shfl_sync(FULL, u, pj0);
            float crow = (lane < NB) ? cw[pj0 * NP1 + lane] : 0.0f;
            bool  act  = (lane < NB) && !used;
            if (act) {
                float cv = crow - u_i0 - v;
                if (cv < minv) { minv = cv; way = j0; }
            }
            unsigned key  = act ? fenc(minv) : ENC_INF;
            unsigned kmin = __reduce_min_sync(FULL, key);
            int j1 = __ffs(__ballot_sync(FULL, key == kmin)) - 1;
            float delta = fdec(kmin);
            if (used)     v    -= delta;
            if (row_used) u    += delta;
            if (act)      minv -= delta;
            j0  = j1;
            pj0 = __shfl_sync(FULL, p, j0);
            if (pj0 < 0) break;
        }
        while (j0 != NB) {
            int jp = __shfl_sync(FULL, way, j0);
            int pv = __shfl_sync(FULL, p, jp);
            if (lane == j0) p = pv;
            j0 = jp;
        }
    }
    if (lane < NB) col_s[w][p] = lane;   // col index of row p[j] is j
    __syncwarp();

    // ---- gather: out[row][:] = slots[col[row]][:] ----
    const float* sb = slots + (size_t)b * NB * ND;
    float*       ob = out   + (size_t)b * NB * ND;
    for (int rr = 0; rr < NB; rr++) {
        int src = col_s[w][rr];
        const float4* s4 = (const float4*)(sb + src * ND);
        float4*       o4 = (float4*)(ob + rr * ND);
        o4[lane]      = s4[lane];
        o4[lane + 32] = s4[lane + 32];
    }
}

extern "C" void kernel_launch(void* const* d_in, const int* in_sizes, int n_in,
                              void* d_out, int out_size) {
    const float* slots = (const float*)d_in[0];
    const float* prev  = (const float*)d_in[1];
    float* out = (float*)d_out;
    int B = in_sizes[0] / (NB * ND);
    if (B > MAXB) B = MAXB;

    // (attribute also set in static ctor; harmless to repeat outside capture? no — keep ctor-only)
    costk<<<B, 144, SMEM_COST>>>(slots, prev, B);

    int grid2 = (B + 3) / 4;
    jvk<<<grid2, 128>>>(slots, out, B);
}

// round 17
// speedup vs baseline: 1.6850x; 1.6850x over previous
#include <cuda_runtime.h>
#include <cstdint>

#define NB    24
#define NP1   25
#define NCOST (NB * NP1)      // 600 floats per batch
#define ND    256
#define INFX  1e9f
#define FULL  0xffffffffu
#define MAXB  2048

// cost scratch: [B][24][25] fp32 (~4.9 MB), static device array (no allocs)
__device__ float g_cost[(size_t)MAXB * NCOST];

// packed fp32x2 FMA (sm_100+); doubles are 64-bit carriers for f32 pairs
__device__ __forceinline__ double ffma2(double a, double b, double c) {
    double r;
    asm("fma.rn.f32x2 %0, %1, %2, %3;" : "=d"(r) : "d"(a), "d"(b), "d"(c));
    return r;
}
__device__ __forceinline__ float pairsum(double a) {
    return __int_as_float(__double2loint(a)) + __int_as_float(__double2hiint(a));
}
// order-preserving float<->uint for unsigned min-reduction
__device__ __forceinline__ unsigned fenc(float x) {
    unsigned b = __float_as_uint(x);
    return b ^ (((unsigned)((int)b >> 31)) | 0x80000000u);
}
__device__ __forceinline__ float fdec(unsigned k) {
    unsigned m = ((unsigned)((int)(~k) >> 31)) | 0x80000000u;
    return __uint_as_float(k ^ m);
}

// 8-stream folded warp reduction (validated): lane L ends holding the sum of
// stream m(L) = bit4(L) | bit3(L)<<1 | bit2(L)<<2.
__device__ __forceinline__ float fold8(
    float q0, float q1, float q2, float q3,
    float q4, float q5, float q6, float q7, int lane)
{
    q0 += __shfl_xor_sync(FULL, q0, 16);
    q1 += __shfl_xor_sync(FULL, q1, 16);
    q2 += __shfl_xor_sync(FULL, q2, 16);
    q3 += __shfl_xor_sync(FULL, q3, 16);
    q4 += __shfl_xor_sync(FULL, q4, 16);
    q5 += __shfl_xor_sync(FULL, q5, 16);
    q6 += __shfl_xor_sync(FULL, q6, 16);
    q7 += __shfl_xor_sync(FULL, q7, 16);
    float t0 = (lane & 16) ? q1 : q0;
    float t1 = (lane & 16) ? q3 : q2;
    float t2 = (lane & 16) ? q5 : q4;
    float t3 = (lane & 16) ? q7 : q6;
    t0 += __shfl_xor_sync(FULL, t0, 8);
    t1 += __shfl_xor_sync(FULL, t1, 8);
    t2 += __shfl_xor_sync(FULL, t2, 8);
    t3 += __shfl_xor_sync(FULL, t3, 8);
    float u0 = (lane & 8) ? t1 : t0;
    float u1 = (lane & 8) ? t3 : t2;
    u0 += __shfl_xor_sync(FULL, u0, 4);
    u1 += __shfl_xor_sync(FULL, u1, 4);
    float v = (lane & 4) ? u1 : u0;
    v += __shfl_xor_sync(FULL, v, 2);
    v += __shfl_xor_sync(FULL, v, 1);
    return v;
}

// ============================================================================
// Kernel 1 (cost): CTA = one batch, 96 threads (3 warps).
// Warp w owns i-block of EIGHT prev rows in registers (halves cur LDS traffic
// vs the 6-warp/4-row layout: 144 vs 288 LDS.128 per batch; shfl/FMA totals
// unchanged; cost values bit-identical).
//  A: stage cur tile -> smem (coalesced burst)
//  B: norms: two fold8 (8 prev + 8 cur streams per warp)
//  C: 6 j-blocks of 4: 8 LDS.128, 32 dots via ffma2, four fold8, writers emit.
// ============================================================================
__global__ __launch_bounds__(96) void costk(
    const float* __restrict__ slots,
    const float* __restrict__ prev,
    int B)
{
    __shared__ float cur_s[NB * ND];     // 24.5 KB staged cur tile
    __shared__ float ipn_s[NB];
    __shared__ float icn_s[NB];

    const int tid  = threadIdx.x;
    const int lane = tid & 31;
    const int w    = tid >> 5;           // 0..2
    const int b    = blockIdx.x;

    const float* sb = slots + (size_t)b * NB * ND;
    const float* pb = prev  + (size_t)b * NB * ND;

    // ---- A: stage cur tile (1536 float4, 16 per thread, coalesced) ----
    {
        const float4* g4 = (const float4*)sb;
        float4* s4 = (float4*)cur_s;
        #pragma unroll
        for (int idx = tid; idx < NB * ND / 4; idx += 96)
            s4[idx] = g4[idx];
    }
    __syncthreads();

    // ---- B: 8 prev rows into registers + 16 inverse norms (two fold8) ----
    const int i0 = w * 8;
    double2 P[8][2];
    {
        float np[8], nc[8];
        #pragma unroll
        for (int r = 0; r < 8; r++) {
            const double2* pr = (const double2*)(pb + (i0 + r) * ND);
            P[r][0] = pr[lane];
            P[r][1] = pr[lane + 32];
            double an = 0.0;
            an = ffma2(P[r][0].x, P[r][0].x, an);
            an = ffma2(P[r][0].y, P[r][0].y, an);
            an = ffma2(P[r][1].x, P[r][1].x, an);
            an = ffma2(P[r][1].y, P[r][1].y, an);
            np[r] = pairsum(an);
            const double2* cr = (const double2*)(cur_s + (i0 + r) * ND);
            double2 c0 = cr[lane], c1 = cr[lane + 32];
            double cn = 0.0;
            cn = ffma2(c0.x, c0.x, cn);
            cn = ffma2(c0.y, c0.y, cn);
            cn = ffma2(c1.x, c1.x, cn);
            cn = ffma2(c1.y, c1.y, cn);
            nc[r] = pairsum(cn);
        }
        float vp = fold8(np[0], np[1], np[2], np[3],
                         np[4], np[5], np[6], np[7], lane);
        float vc = fold8(nc[0], nc[1], nc[2], nc[3],
                         nc[4], nc[5], nc[6], nc[7], lane);
        if ((lane & 3) == 0) {
            int m = ((lane >> 4) & 1) | (((lane >> 3) & 1) << 1) | (((lane >> 2) & 1) << 2);
            ipn_s[i0 + m] = 1.0f / fmaxf(sqrtf(vp), 1e-12f);
            icn_s[i0 + m] = 1.0f / fmaxf(sqrtf(vc), 1e-12f);
        }
    }
    __syncthreads();

    // ---- C: 6 j-blocks of 4 cur rows (smem), 32 dots -> four fold8 ----
    {
        const int m = ((lane >> 4) & 1) | (((lane >> 3) & 1) << 1) | (((lane >> 2) & 1) << 2);
        const int a = m >> 2;       // 0..1
        const int c = m & 3;        // 0..3
        const bool writer = ((lane & 3) == 0);
        float ipn1 = 0.f, ipn2 = 0.f, ipn3 = 0.f, ipn4 = 0.f;
        if (writer) {
            ipn1 = ipn_s[i0 + a];
            ipn2 = ipn_s[i0 + 2 + a];
            ipn3 = ipn_s[i0 + 4 + a];
            ipn4 = ipn_s[i0 + 6 + a];
        }
        float* gc = g_cost + (size_t)b * NCOST;

        #pragma unroll
        for (int t = 0; t < 6; t++) {
            const int j0 = t * 4;
            double2 C0[4], C1[4];
            #pragma unroll
            for (int r = 0; r < 4; r++) {
                const double2* cr = (const double2*)(cur_s + (j0 + r) * ND);
                C0[r] = cr[lane];
                C1[r] = cr[lane + 32];
            }
            #pragma unroll
            for (int half = 0; half < 4; half++) {
                const int ra = half * 2;     // rows ra, ra+1
                float s[8];
                #pragma unroll
                for (int aa = 0; aa < 2; aa++) {
                    #pragma unroll
                    for (int cc = 0; cc < 4; cc++) {
                        double acc = 0.0;
                        acc = ffma2(P[ra + aa][0].x, C0[cc].x, acc);
                        acc = ffma2(P[ra + aa][0].y, C0[cc].y, acc);
                        acc = ffma2(P[ra + aa][1].x, C1[cc].x, acc);
                        acc = ffma2(P[ra + aa][1].y, C1[cc].y, acc);
                        s[aa * 4 + cc] = pairsum(acc);
                    }
                }
                float v = fold8(s[0], s[1], s[2], s[3], s[4], s[5], s[6], s[7], lane);
                if (writer) {
                    float ipn = (half == 0) ? ipn1 : (half == 1) ? ipn2
                              : (half == 2) ? ipn3 : ipn4;
                    gc[(i0 + ra + a) * NP1 + (j0 + c)] = 1.0f - v * ipn * icn_s[j0 + c];
                }
            }
        }
    }
}

// ============================================================================
// Kernel 2: JV Hungarian + gather. One warp per batch, 4 warps/CTA.
// Byte-identical to the validated R10 version.
// ============================================================================
__global__ __launch_bounds__(128) void jvk(
    const float* __restrict__ slots,
    float* __restrict__ out,
    int B)
{
    __shared__ float cost_s[4][NCOST];
    __shared__ int   col_s[4][NB];

    const int lane = threadIdx.x & 31;
    const int w    = threadIdx.x >> 5;
    const int b    = blockIdx.x * 4 + w;
    if (b >= B) return;

    // ---- stage this batch's cost matrix into smem (600 floats) ----
    {
        const float4* gc4 = (const float4*)(g_cost + (size_t)b * NCOST);
        float4* cs4 = (float4*)cost_s[w];
        #pragma unroll
        for (int t = lane; t < NCOST / 4; t += 32)
            cs4[t] = gc4[t];
    }
    __syncwarp();

    const float* cw = cost_s[w];
    const unsigned ENC_INF = fenc(INFX);

    float u = 0.0f, v = 0.0f;
    int   p = -1;
    unsigned rowmask = 0;       // bit r set => row r matched

    // ---- column reduction: v[j] = min_i c[i][j]; greedy argmin matching ----
    {
        int rmin = 32 + lane;   // unique sentinel for lanes >= NB
        if (lane < NB) {
            float m = INFX;
            rmin = 0;
            #pragma unroll
            for (int i = 0; i < NB; i++) {
                float c = cw[i * NP1 + lane];
                if (c < m) { m = c; rmin = i; }   // first-index on ties
            }
            v = m;
        }
        unsigned grp = __match_any_sync(FULL, rmin);
        bool claim = (lane < NB) && (lane == __ffs(grp) - 1);  // lowest col wins row
        if (claim) p = rmin;
        rowmask = __reduce_or_sync(FULL, claim ? (1u << rmin) : 0u);
    }

    // ---- augmenting row reduction over still-free rows ----
    {
        unsigned freerows = ~rowmask & ((1u << NB) - 1u);
        while (freerows) {
            int i = __ffs(freerows) - 1;
            freerows &= freerows - 1;
            float rc = (lane < NB) ? cw[i * NP1 + lane] - v : INFX;
            unsigned key  = (lane < NB) ? fenc(rc) : ENC_INF;
            unsigned kmin = __reduce_min_sync(FULL, key);
            int j1 = __ffs(__ballot_sync(FULL, key == kmin)) - 1;
            float ui = fdec(kmin);
            if (lane == i) u = ui;
            int pj1 = __shfl_sync(FULL, p, j1);
            if (pj1 < 0) {                 // column free -> match (i, j1)
                if (lane == j1) p = i;
                rowmask |= 1u << i;
            }
        }
    }

    // ---- augmenting-path searches for remaining free rows (validated) ----
    for (int i = 0; i < NB; i++) {
        if ((rowmask >> i) & 1u) continue;

        if (lane == NB) p = i;
        float minv = INFX;
        int   way  = 0;
        bool  used = false;
        bool  row_used = false;
        int   j0  = NB;
        int   pj0 = i;

        while (true) {
            used     = used     || (lane == j0);
            row_used = row_used || (lane == pj0);
            float u_i0 = __shfl_sync(FULL, u, pj0);
            float crow = (lane < NB) ? cw[pj0 * NP1 + lane] : 0.0f;
            bool  act  = (lane < NB) && !used;
            if (act) {
                float cv = crow - u_i0 - v;
                if (cv < minv) { minv = cv; way = j0; }
            }
            unsigned key  = act ? fenc(minv) : ENC_INF;
            unsigned kmin = __reduce_min_sync(FULL, key);
            int j1 = __ffs(__ballot_sync(FULL, key == kmin)) - 1;
            float delta = fdec(kmin);
            if (used)     v    -= delta;
            if (row_used) u    += delta;
            if (act)      minv -= delta;
            j0  = j1;
            pj0 = __shfl_sync(FULL, p, j0);
            if (pj0 < 0) break;
        }
        while (j0 != NB) {
            int jp = __shfl_sync(FULL, way, j0);
            int pv = __shfl_sync(FULL, p, jp);
            if (lane == j0) p = pv;
            j0 = jp;
        }
    }
    if (lane < NB) col_s[w][p] = lane;   // col index of row p[j] is j
    __syncwarp();

    // ---- gather: out[row][:] = slots[col[row]][:] ----
    const float* sb = slots + (size_t)b * NB * ND;
    float*       ob = out   + (size_t)b * NB * ND;
    for (int rr = 0; rr < NB; rr++) {
        int src = col_s[w][rr];
        const float4* s4 = (const float4*)(sb + src * ND);
        float4*       o4 = (float4*)(ob + rr * ND);
        o4[lane]      = s4[lane];
        o4[lane + 32] = s4[lane + 32];
    }
}

extern "C" void kernel_launch(void* const* d_in, const int* in_sizes, int n_in,
                              void* d_out, int out_size) {
    const float* slots = (const float*)d_in[0];
    const float* prev  = (const float*)d_in[1];
    float* out = (float*)d_out;
    int B = in_sizes[0] / (NB * ND);
    if (B > MAXB) B = MAXB;

    costk<<<B, 96>>>(slots, prev, B);

    int grid2 = (B + 3) / 4;
    jvk<<<grid2, 128>>>(slots, out, B);
}